// round 1
// baseline (speedup 1.0000x reference)
#include <cuda_runtime.h>
#include <cuda_bf16.h>
#include <math.h>

// Problem constants
#define KK   64      // number of tags
#define DD   512     // embedding dim
#define BB   512     // batch (sequences)
#define TT   128     // sequence length
#define BOS_T 63
#define EOS_T 62
#define BT   (BB*TT) // 65536 occurrences

// Scratch: raw emission logits wb[b*T+t][k]  (16 MiB)
__device__ float g_wbdot[(size_t)BT * KK];

// ---------------------------------------------------------------------------
// Kernel 1: emission logits  wb[i][k] = dot(ThetaB[k,:], E[words[i],:])
// Full ThetaB (64x512 fp32 = 128KB) staged in dynamic shared memory.
// One thread per occurrence, 64 fp32 accumulators, K chunked by 16.
// ---------------------------------------------------------------------------
extern __shared__ float sTheta[];   // 32768 floats = 131072 bytes

#define FMA4(ev, tv) { a = fmaf((ev).x,(tv).x,a); a = fmaf((ev).y,(tv).y,a); \
                       a = fmaf((ev).z,(tv).z,a); a = fmaf((ev).w,(tv).w,a); }

__global__ __launch_bounds__(256, 1)
void emit_kernel(const float* __restrict__ ThetaB,
                 const float* __restrict__ E,
                 const int*   __restrict__ words)
{
    // Stage ThetaB -> shared (coalesced float4)
    float4*       s4 = reinterpret_cast<float4*>(sTheta);
    const float4* g4 = reinterpret_cast<const float4*>(ThetaB);
    for (int i = threadIdx.x; i < (KK * DD) / 4; i += 256) s4[i] = g4[i];
    __syncthreads();

    const int i    = blockIdx.x * 256 + threadIdx.x;   // occurrence id (b*T+t)
    const int word = words[i];
    const float4* e4 = reinterpret_cast<const float4*>(E + (long)word * DD);

    float acc[KK];
#pragma unroll
    for (int k = 0; k < KK; ++k) acc[k] = 0.f;

    // 32 chunks of 16 dims
    for (int c = 0; c < DD / 16; ++c) {
        const float4 e0 = e4[c * 4 + 0];
        const float4 e1 = e4[c * 4 + 1];
        const float4 e2 = e4[c * 4 + 2];
        const float4 e3 = e4[c * 4 + 3];
#pragma unroll
        for (int k = 0; k < KK; ++k) {
            const float4* t4 = s4 + k * (DD / 4) + c * 4;  // broadcast LDS
            const float4 t0 = t4[0];
            const float4 t1 = t4[1];
            const float4 t2 = t4[2];
            const float4 t3 = t4[3];
            float a = acc[k];
            FMA4(e0, t0); FMA4(e1, t1); FMA4(e2, t2); FMA4(e3, t3);
            acc[k] = a;
        }
    }

    // Each thread writes its own 256B contiguous run (full sectors)
    float4* o4 = reinterpret_cast<float4*>(g_wbdot + (long)i * KK);
#pragma unroll
    for (int k = 0; k < KK / 4; ++k)
        o4[k] = make_float4(acc[4*k], acc[4*k+1], acc[4*k+2], acc[4*k+3]);
}

// ---------------------------------------------------------------------------
// Kernel 2: per-sequence result.
//   tagged (closed form):  WA[BOS,tag1] + sum WA[tag_{t-1},tag_t]
//                          + sum wb[t,tag_t] + WA[tag126,EOS]
//   unsup  (forward with fixed 1/64 rescale):
//          logZ = log(alpha_126 . A[:,EOS]) + 126*log(64)
// One block (64 threads) per sequence; A column in registers; alpha broadcast
// via double-buffered shared (1 sync per step).
// ---------------------------------------------------------------------------
__device__ __forceinline__ float block_sum64(float v, volatile float* sh)
{
#pragma unroll
    for (int o = 16; o > 0; o >>= 1)
        v += __shfl_down_sync(0xffffffffu, v, o);
    if ((threadIdx.x & 31) == 0) sh[threadIdx.x >> 5] = v;
    __syncthreads();
    float r = sh[0] + sh[1];
    __syncthreads();
    return r;
}

__global__ __launch_bounds__(64, 8)
void forward_kernel(const float* __restrict__ WA,
                    const int*   __restrict__ tags,
                    float*       __restrict__ out)
{
    __shared__ float sA[2][KK];
    __shared__ float sred[2];

    const int k = threadIdx.x;
    const int b = blockIdx.x;

    // A column k in registers: Acol[j] = exp(WA[j][k]); column BOS forced to 0
    float Acol[KK];
#pragma unroll
    for (int j = 0; j < KK; ++j) {
        float w = WA[j * KK + k];
        Acol[j] = (k == BOS_T) ? 0.f : expf(w);
    }

    // ---- tagged path (closed form, cooperative over t) ----
    const int* tg = tags + b * TT;
    float part = 0.f;
    for (int t = k + 1; t <= 126; t += KK) {
        const int c = tg[t];
        const int p = (t == 1) ? BOS_T : tg[t - 1];
        part += WA[p * KK + c] + g_wbdot[((long)(b * TT + t)) * KK + c];
    }
    if (k == 0) part += WA[tg[126] * KK + EOS_T];
    const float tagged = block_sum64(part, sred);

    // ---- unsupervised forward ----
    const float inv = 1.0f / 64.0f;
    // step t=1: alpha0 is delta at BOS -> alpha1[k] = A[BOS,k]*e1[k]/64
    {
        const float wb = g_wbdot[((long)(b * TT + 1)) * KK + k];
        const float e  = (k >= EOS_T) ? 0.f : expf(wb);
        // note: for k==BOS_T, Acol is zeroed but e is 0 anyway
    }
    float wb1 = g_wbdot[((long)(b * TT + 1)) * KK + k];
    float e1  = (k >= EOS_T) ? 0.f : expf(wb1);
    float alph = Acol[BOS_T] * e1 * inv;

    int buf = 0;
    for (int t = 2; t <= 126; ++t) {
        sA[buf][k] = alph;
        __syncthreads();
        // prefetch emission logit for this step
        const float wb = g_wbdot[((long)(b * TT + t)) * KK + k];
        // matvec: s = sum_j alpha[j] * A[j][k], 4-way split accumulators
        const float4* a4 = reinterpret_cast<const float4*>(sA[buf]);
        float s0 = 0.f, s1 = 0.f, s2 = 0.f, s3 = 0.f;
#pragma unroll
        for (int jj = 0; jj < KK / 4; ++jj) {
            const float4 v = a4[jj];
            s0 = fmaf(v.x, Acol[4*jj+0], s0);
            s1 = fmaf(v.y, Acol[4*jj+1], s1);
            s2 = fmaf(v.z, Acol[4*jj+2], s2);
            s3 = fmaf(v.w, Acol[4*jj+3], s3);
        }
        const float s = (s0 + s1) + (s2 + s3);
        const float e = (k >= EOS_T) ? 0.f : expf(wb);
        alph = s * inv * e;
        buf ^= 1;
        // no second sync needed: next iteration writes the OTHER buffer,
        // and its sync fences this iteration's reads before the wraparound.
    }

    // final transition into EOS: val = sum_k alpha[k] * A[k][EOS]
    const float aeos    = expf(WA[k * KK + EOS_T]);
    const float contrib = alph * aeos;
    const float val     = block_sum64(contrib, sred);

    if (k == 0) {
        const float logZ_unsup = logf(val) + 126.0f * logf(64.0f);
        out[b] = tagged - logZ_unsup;
    }
}

// ---------------------------------------------------------------------------
// Launch
// Inputs (metadata order): WA[64*64] f32, ThetaB[64*512] f32, E[100000*512] f32,
//                          words[512*128] i32, tags[512*128] i32
// Output: f32[512]
// ---------------------------------------------------------------------------
extern "C" void kernel_launch(void* const* d_in, const int* in_sizes, int n_in,
                              void* d_out, int out_size)
{
    const float* WA     = (const float*)d_in[0];
    const float* ThetaB = (const float*)d_in[1];
    const float* E      = (const float*)d_in[2];
    const int*   words  = (const int*)d_in[3];
    const int*   tags   = (const int*)d_in[4];
    float*       out    = (float*)d_out;

    const int smem = KK * DD * (int)sizeof(float);  // 131072 bytes
    cudaFuncSetAttribute(emit_kernel,
                         cudaFuncAttributeMaxDynamicSharedMemorySize, smem);

    emit_kernel<<<BT / 256, 256, smem>>>(ThetaB, E, words);
    forward_kernel<<<BB, KK>>>(WA, tags, out);
}

// round 5
// speedup vs baseline: 1.4590x; 1.4590x over previous
#include <cuda_runtime.h>
#include <cuda_bf16.h>
#include <math.h>
#include <stdint.h>

// Problem constants
#define KK    64
#define DD    512
#define TT    128
#define BOS_T 63
#define EOS_T 62
#define LOG64 4.158883083359672f

#define STR   68              // padded row stride in 4B words (136 bf16 / 68 f32 = 272B)

// SMEM layout (bytes from dynamic base)
#define OFF_A   0             // gathered E chunk: 128 rows x 272B = 34816
#define OFF_B   34816         // ThetaB chunk:      64 rows x 272B = 17408
#define OFF_SWB 52224         // exp(wb)/64:       128 rows x 272B = 34816
#define OFF_SAL 87040         // alpha double buffer: 2 x 64 f32 = 512
#define OFF_RED 87552         // reduction scratch: 32 f32 = 128
#define SMEM_DYN 87680

__device__ __forceinline__ uint32_t pk(float a, float b) {
    __nv_bfloat162 h = __floats2bfloat162_rn(a, b);
    return *reinterpret_cast<uint32_t*>(&h);
}

__device__ __forceinline__ void mma16816(float* c, uint32_t a0, uint32_t a1,
                                         uint32_t a2, uint32_t a3,
                                         uint32_t b0, uint32_t b1) {
    asm volatile(
        "mma.sync.aligned.m16n8k16.row.col.f32.bf16.bf16.f32 "
        "{%0,%1,%2,%3}, {%4,%5,%6,%7}, {%8,%9}, {%0,%1,%2,%3};"
        : "+f"(c[0]), "+f"(c[1]), "+f"(c[2]), "+f"(c[3])
        : "r"(a0), "r"(a1), "r"(a2), "r"(a3), "r"(b0), "r"(b1));
}

// ---------------------------------------------------------------------------
// One CTA per sequence:
//  1) gather E rows + ThetaB -> bf16 SMEM (padded), warp-level bf16 MMA
//     accumulating wb[128x64] in registers (K=512, 4 chunks)
//  2) epilogue: swb = exp(wb)/64 (BOS/EOS cols zeroed); tagged closed form
//  3) 125-step forward recursion on SMEM, 256-thread cooperative matvec
// ---------------------------------------------------------------------------
__global__ __launch_bounds__(256, 2)
void crf_fused_kernel(const float* __restrict__ WA,
                      const float* __restrict__ ThetaB,
                      const float* __restrict__ E,
                      const int*   __restrict__ words,
                      const int*   __restrict__ tags,
                      float*       __restrict__ out)
{
    extern __shared__ char sm[];
    uint32_t* A32  = (uint32_t*)(sm + OFF_A);
    uint32_t* B32  = (uint32_t*)(sm + OFF_B);
    float*    swb  = (float*)(sm + OFF_SWB);
    float*    sal  = (float*)(sm + OFF_SAL);
    float*    sred = (float*)(sm + OFF_RED);

    const int tid  = threadIdx.x;
    const int wid  = tid >> 5, lane = tid & 31;
    const int g    = lane >> 2, t4 = lane & 3;
    const int b    = blockIdx.x;
    const int m0   = wid * 16;

    // gather assignments
    const int arow = tid >> 1, ahalf = tid & 1;          // A: 2 thr/row, 64 f32 each
    const int brow = tid >> 2, bq = tid & 3;             // B: 4 thr/row, 32 f32 each
    const int word = words[b * TT + arow];
    const float* eptr = E + (size_t)word * DD + ahalf * 64;
    const float* tptr = ThetaB + brow * DD + bq * 32;

    float acc[8][4];
#pragma unroll
    for (int nt = 0; nt < 8; ++nt)
#pragma unroll
        for (int r = 0; r < 4; ++r) acc[nt][r] = 0.f;

    // ---- mainloop: 4 K-chunks of 128 ----
    for (int c = 0; c < 4; ++c) {
        if (c) __syncthreads();                          // SMEM reusable

        const float4* e4 = (const float4*)(eptr + c * 128);
#pragma unroll
        for (int i = 0; i < 8; ++i) {
            float4 f0 = e4[2 * i], f1 = e4[2 * i + 1];
            *(uint4*)(sm + OFF_A + arow * 272 + ahalf * 128 + i * 16) =
                make_uint4(pk(f0.x, f0.y), pk(f0.z, f0.w), pk(f1.x, f1.y), pk(f1.z, f1.w));
        }
        const float4* th4 = (const float4*)(tptr + c * 128);
#pragma unroll
        for (int i = 0; i < 4; ++i) {
            float4 f0 = th4[2 * i], f1 = th4[2 * i + 1];
            *(uint4*)(sm + OFF_B + brow * 272 + bq * 64 + i * 16) =
                make_uint4(pk(f0.x, f0.y), pk(f0.z, f0.w), pk(f1.x, f1.y), pk(f1.z, f1.w));
        }
        __syncthreads();

        // 8 k16-steps x 8 n-tiles of m16n8k16
#pragma unroll
        for (int s = 0; s < 8; ++s) {
            const uint32_t a0 = A32[(m0 + g)     * STR + s * 8 + t4];
            const uint32_t a1 = A32[(m0 + 8 + g) * STR + s * 8 + t4];
            const uint32_t a2 = A32[(m0 + g)     * STR + s * 8 + t4 + 4];
            const uint32_t a3 = A32[(m0 + 8 + g) * STR + s * 8 + t4 + 4];
#pragma unroll
            for (int nt = 0; nt < 8; ++nt) {
                const uint32_t b0 = B32[(nt * 8 + g) * STR + s * 8 + t4];
                const uint32_t b1 = B32[(nt * 8 + g) * STR + s * 8 + t4 + 4];
                mma16816(acc[nt], a0, a1, a2, a3, b0, b1);
            }
        }
    }
    __syncthreads();

    // ---- epilogue: swb = exp(wb)/64, BOS/EOS cols -> 0 ----
    const float inv = 1.0f / 64.0f;
    const int r0 = m0 + g, r1 = m0 + 8 + g;
#pragma unroll
    for (int nt = 0; nt < 8; ++nt) {
        const int col = nt * 8 + t4 * 2;
        const bool msk = (col == EOS_T);                 // covers cols 62,63 pair
        float2 v0, v1;
        v0.x = msk ? 0.f : __expf(acc[nt][0]) * inv;
        v0.y = msk ? 0.f : __expf(acc[nt][1]) * inv;
        v1.x = msk ? 0.f : __expf(acc[nt][2]) * inv;
        v1.y = msk ? 0.f : __expf(acc[nt][3]) * inv;
        *(float2*)(swb + r0 * STR + col) = v0;
        *(float2*)(swb + r1 * STR + col) = v1;
    }
    __syncthreads();

    // ---- tagged closed form ----
    float tagc = 0.f;
    if (tid >= 1 && tid <= 126) {
        const int ct = tags[b * TT + tid];
        const int pt = (tid == 1) ? BOS_T : tags[b * TT + tid - 1];
        tagc = __logf(swb[tid * STR + ct]) + LOG64 + WA[pt * KK + ct];
    } else if (tid == 127) {
        tagc = WA[tags[b * TT + 126] * KK + EOS_T];
    }
#pragma unroll
    for (int o = 16; o > 0; o >>= 1) tagc += __shfl_down_sync(0xffffffffu, tagc, o);
    if (lane == 0) sred[wid] = tagc;
    __syncthreads();
    if (tid == 0) {
        float s = 0.f;
        for (int w = 0; w < 8; ++w) s += sred[w];
        sred[8] = s;
    }

    // ---- forward recursion: output k = 8*wid + g, j-split over t4 ----
    const int fk = wid * 8 + g;
    float Areg[16];
#pragma unroll
    for (int jj = 0; jj < 16; ++jj)
        Areg[jj] = __expf(WA[(t4 * 16 + jj) * KK + fk]);

    if (t4 == 0) sal[fk] = __expf(WA[BOS_T * KK + fk]) * swb[1 * STR + fk];
    __syncthreads();

    int buf = 0;
    for (int t = 2; t <= 126; ++t) {
        const float4* av = (const float4*)(sal + buf * KK + t4 * 16);
        float s0 = 0.f, s1 = 0.f, s2 = 0.f, s3 = 0.f;
#pragma unroll
        for (int jj = 0; jj < 4; ++jj) {
            const float4 v = av[jj];
            s0 = fmaf(v.x, Areg[4 * jj + 0], s0);
            s1 = fmaf(v.y, Areg[4 * jj + 1], s1);
            s2 = fmaf(v.z, Areg[4 * jj + 2], s2);
            s3 = fmaf(v.w, Areg[4 * jj + 3], s3);
        }
        float s = (s0 + s1) + (s2 + s3);
        s += __shfl_xor_sync(0xffffffffu, s, 1);
        s += __shfl_xor_sync(0xffffffffu, s, 2);
        if (t4 == 0) sal[(buf ^ 1) * KK + fk] = s * swb[t * STR + fk];
        __syncthreads();
        buf ^= 1;
    }

    float contrib = 0.f;
    if (tid < 64) contrib = sal[buf * KK + tid] * __expf(WA[tid * KK + EOS_T]);
#pragma unroll
    for (int o = 16; o > 0; o >>= 1) contrib += __shfl_down_sync(0xffffffffu, contrib, o);
    if (tid < 64 && lane == 0) sred[16 + wid] = contrib;
    __syncthreads();
    if (tid == 0)
        out[b] = sred[8] - (__logf(sred[16] + sred[17]) + 126.0f * LOG64);
}

// ---------------------------------------------------------------------------
// Inputs: WA[64*64] f32, ThetaB[64*512] f32, E[100000*512] f32,
//         words[512*128] i32, tags[512*128] i32  ->  out f32[512]
// ---------------------------------------------------------------------------
extern "C" void kernel_launch(void* const* d_in, const int* in_sizes, int n_in,
                              void* d_out, int out_size)
{
    const float* WA     = (const float*)d_in[0];
    const float* ThetaB = (const float*)d_in[1];
    const float* E      = (const float*)d_in[2];
    const int*   words  = (const int*)d_in[3];
    const int*   tags   = (const int*)d_in[4];
    float*       out    = (float*)d_out;

    static int attr_done = 0;
    if (!attr_done) {
        cudaFuncSetAttribute(crf_fused_kernel,
                             cudaFuncAttributeMaxDynamicSharedMemorySize, SMEM_DYN);
        attr_done = 1;
    }
    crf_fused_kernel<<<512, 256, SMEM_DYN>>>(WA, ThetaB, E, words, tags, out);
}